// round 3
// baseline (speedup 1.0000x reference)
#include <cuda_runtime.h>
#include <cuda_bf16.h>

#define BINS 64
#define ROWS 96                 // B*C = 32*3
#define HW   262144             // 512*512
#define BLOCKS_PER_ROW 16
#define NBLOCKS (ROWS * BLOCKS_PER_ROW)
#define THREADS 256
#define WARPS (THREADS / 32)
#define TSTRIDE 17              // words per thread region (padded: 17 coprime w/ 32 banks)

// Signed diff histogram scratch (fake − real), per (b,c) row.
__device__ int g_diff[ROWS * BINS];
__device__ unsigned int g_done;

__device__ __forceinline__ int bin_of(float x) {
    x = __saturatef(x);                 // clip [0,1]
    int i = (int)(x * 64.0f);           // exact pow2 scale, trunc == astype(int32)
    return i > 63 ? 63 : i;
}

__global__ __launch_bounds__(THREADS) void hist_loss_kernel(
    const float4* __restrict__ fake, const float4* __restrict__ real_,
    float* __restrict__ out)
{
    // Per-thread packed byte counters: 16 words = 64 bins, bias 64 per byte.
    __shared__ unsigned int sh[THREADS * TSTRIDE];     // 17408 B
    __shared__ int sh_part[THREADS];                   // quarter-partials
    __shared__ int warp_sums[WARPS];
    __shared__ int is_last;

    const int tid = threadIdx.x;
    const unsigned base = tid * TSTRIDE;

    // init: every byte = 64 (0x40)
    #pragma unroll
    for (int i = tid; i < THREADS * TSTRIDE; i += THREADS)
        sh[i] = 0x40404040u;
    __syncthreads();

    const int row = blockIdx.x / BLOCKS_PER_ROW;
    const int seg = blockIdx.x % BLOCKS_PER_ROW;
    const int vec_per_row = HW / 4;                       // 65536 float4
    const int vec_per_seg = vec_per_row / BLOCKS_PER_ROW; // 4096 float4 (16/thread)
    const long gbase = (long)row * vec_per_row + (long)seg * vec_per_seg;

    #pragma unroll 2
    for (int i = tid; i < vec_per_seg; i += THREADS) {
        float4 f = fake[gbase + i];
        float4 r = real_[gbase + i];
        int b;
        b = bin_of(f.x); sh[base + (b >> 2)] += 1u << ((b & 3) << 3);
        b = bin_of(f.y); sh[base + (b >> 2)] += 1u << ((b & 3) << 3);
        b = bin_of(f.z); sh[base + (b >> 2)] += 1u << ((b & 3) << 3);
        b = bin_of(f.w); sh[base + (b >> 2)] += 1u << ((b & 3) << 3);
        b = bin_of(r.x); sh[base + (b >> 2)] -= 1u << ((b & 3) << 3);
        b = bin_of(r.y); sh[base + (b >> 2)] -= 1u << ((b & 3) << 3);
        b = bin_of(r.z); sh[base + (b >> 2)] -= 1u << ((b & 3) << 3);
        b = bin_of(r.w); sh[base + (b >> 2)] -= 1u << ((b & 3) << 3);
    }
    __syncthreads();

    // Expand + reduce: thread handles (bin = tid&63) over one quarter of threads.
    {
        const unsigned char* shb = (const unsigned char*)sh;
        const int b = tid & 63;
        const int q = tid >> 6;                 // 4 quarters of 64 threads
        int s = 0;
        #pragma unroll 8
        for (int t = q * 64; t < q * 64 + 64; ++t)
            s += (int)shb[t * (TSTRIDE * 4) + b];
        s -= 64 * 64;                           // remove bias
        sh_part[tid] = s;
    }
    __syncthreads();
    if (tid < BINS) {
        int tot = sh_part[tid] + sh_part[64 + tid] + sh_part[128 + tid] + sh_part[192 + tid];
        if (tot != 0) atomicAdd(&g_diff[row * BINS + tid], tot);
    }

    // Completion: last block does the final |diff| reduction + cleanup.
    __threadfence();
    if (tid == 0) {
        unsigned int prev = atomicAdd(&g_done, 1u);
        is_last = (prev == NBLOCKS - 1) ? 1 : 0;
    }
    __syncthreads();
    if (!is_last) return;

    // ---- Last block only ----  (max |total| = 2*ROWS*HW < 2^31, int safe)
    int s = 0;
    for (int i = tid; i < ROWS * BINS; i += THREADS) {
        int v = g_diff[i];
        g_diff[i] = 0;                          // re-zero for next replay
        s += (v < 0) ? -v : v;
    }
    #pragma unroll
    for (int off = 16; off > 0; off >>= 1)
        s += __shfl_down_sync(0xFFFFFFFFu, s, off);
    if ((tid & 31) == 0) warp_sums[tid >> 5] = s;
    __syncthreads();
    if (tid == 0) {
        int total = 0;
        #pragma unroll
        for (int w = 0; w < WARPS; w++) total += warp_sums[w];
        out[0] = (float)((double)total / ((double)HW * (double)(ROWS * BINS)));
        g_done = 0;                             // reset for next replay
    }
}

extern "C" void kernel_launch(void* const* d_in, const int* in_sizes, int n_in,
                              void* d_out, int out_size) {
    const float4* fake  = (const float4*)d_in[0];
    const float4* real_ = (const float4*)d_in[1];
    float* out = (float*)d_out;
    hist_loss_kernel<<<NBLOCKS, THREADS>>>(fake, real_, out);
}